// round 9
// baseline (speedup 1.0000x reference)
#include <cuda_runtime.h>
#include <cuda_fp16.h>
#include <cstdint>
#include <math.h>

#define NE    16
#define DIN   256
#define DH    512
#define DOUT  256
#define NB    32768
#define BM    128
#define MAXT  544

// ---------------- persistent device scratch ----------------
__device__ int   g_cnt[NE];
__device__ int   g_tok[NE * NB];
__device__ float g_wt [NE * NB];
__device__ int   g_ntiles;
__device__ int   g_tile[MAXT];                 // (e<<20) | mbase
__device__ __align__(16) __half g_x [NB * DIN];
__device__ __align__(16) __half g_w1[NE * DH * DIN];   // [e][n][k]
__device__ __align__(16) __half g_w2[NE * DOUT * DH];  // [e][n][k]

// ---------------- helpers ----------------
__device__ __forceinline__ uint32_t smem_to_u32(const void* p) {
    uint32_t a;
    asm("{ .reg .u64 t; cvta.to.shared.u64 t, %1; cvt.u32.u64 %0, t; }" : "=r"(a) : "l"(p));
    return a;
}
__device__ __forceinline__ void ldmat4(uint32_t* r, uint32_t addr) {
    asm volatile("ldmatrix.sync.aligned.m8n8.x4.shared.b16 {%0,%1,%2,%3}, [%4];"
        : "=r"(r[0]), "=r"(r[1]), "=r"(r[2]), "=r"(r[3]) : "r"(addr));
}
__device__ __forceinline__ void mma16816(float* c, const uint32_t* a, const uint32_t* b) {
    asm volatile("mma.sync.aligned.m16n8k16.row.col.f32.f16.f16.f32 "
        "{%0,%1,%2,%3},{%4,%5,%6,%7},{%8,%9},{%0,%1,%2,%3};"
        : "+f"(c[0]), "+f"(c[1]), "+f"(c[2]), "+f"(c[3])
        : "r"(a[0]), "r"(a[1]), "r"(a[2]), "r"(a[3]), "r"(b[0]), "r"(b[1]));
}
__device__ __forceinline__ uint32_t pack2h(__half a, __half b) {
    return (uint32_t)__half_as_ushort(a) | ((uint32_t)__half_as_ushort(b) << 16);
}
__device__ __forceinline__ void cp16(uint32_t s, const void* g) {
    asm volatile("cp.async.cg.shared.global [%0], [%1], 16;" :: "r"(s), "l"(g));
}
#define CP_COMMIT() asm volatile("cp.async.commit_group;" ::: "memory")
#define CP_WAIT0()  asm volatile("cp.async.wait_group 0;" ::: "memory")

// ---------------- small kernels ----------------
__global__ void zero_cnt_kernel() { if (threadIdx.x < NE) g_cnt[threadIdx.x] = 0; }

__global__ void build_tiles_kernel() {
    int nt = 0;
    for (int e = 0; e < NE; e++) {
        int c = g_cnt[e];
        for (int mb = 0; mb < c; mb += BM) g_tile[nt++] = (e << 20) | mb;
    }
    g_ntiles = nt;
}

// gating + fused fp32->fp16 conversion of x
__global__ void gating_kernel(const float* __restrict__ x,
                              const float* __restrict__ Wg,
                              const float* __restrict__ bg) {
    __shared__ float sWgT[NE * DIN];
    int tid = threadIdx.x;
    #pragma unroll
    for (int i = 0; i < NE * DIN / 256; i++) {
        int idx = tid + i * 256;
        int d = idx >> 4, e = idx & 15;
        sWgT[e * DIN + d] = Wg[idx];
    }
    __syncthreads();
    int warp = tid >> 5, lane = tid & 31;
    int token = blockIdx.x * 8 + warp;
    float xv[8];
    #pragma unroll
    for (int i = 0; i < 8; i++) xv[i] = x[(size_t)token * DIN + lane + 32 * i];
    #pragma unroll
    for (int i = 0; i < 8; i++)
        g_x[(size_t)token * DIN + lane + 32 * i] = __float2half_rn(xv[i]);
    float logit[NE];
    #pragma unroll
    for (int e = 0; e < NE; e++) {
        float s = 0.f;
        #pragma unroll
        for (int i = 0; i < 8; i++) s += xv[i] * sWgT[e * DIN + lane + 32 * i];
        #pragma unroll
        for (int off = 16; off > 0; off >>= 1) s += __shfl_xor_sync(0xffffffffu, s, off);
        logit[e] = s + bg[e];
    }
    float m1 = -1e30f, m2 = -1e30f; int i1 = 0, i2 = 0;
    #pragma unroll
    for (int e = 0; e < NE; e++) {
        float v = logit[e];
        if (v > m1)      { m2 = m1; i2 = i1; m1 = v; i1 = e; }
        else if (v > m2) { m2 = v;  i2 = e; }
    }
    float r  = expf(m2 - m1);
    float w0 = 1.f / (1.f + r);
    float w1 = 1.f - w0;
    if (lane == 0) {
        int p  = atomicAdd(&g_cnt[i1], 1);
        g_tok[i1 * NB + p] = token;  g_wt[i1 * NB + p] = w0;
        int p2 = atomicAdd(&g_cnt[i2], 1);
        g_tok[i2 * NB + p2] = token; g_wt[i2 * NB + p2] = w1;
    }
}

// W1 [e][k=256][n=512] -> transposed fp16 [e][n][k]
__global__ void convert_w1_kernel(const float* __restrict__ W) {
    __shared__ float t[32][33];
    int e = blockIdx.z, k0 = blockIdx.x * 32, n0 = blockIdx.y * 32;
    int tx = threadIdx.x, ty = threadIdx.y;
    #pragma unroll
    for (int i = 0; i < 32; i += 8)
        t[ty + i][tx] = W[((size_t)e * DIN + k0 + ty + i) * DH + n0 + tx];
    __syncthreads();
    #pragma unroll
    for (int i = 0; i < 32; i += 8) {
        size_t o = ((size_t)e * DH + n0 + ty + i) * DIN + k0 + tx;
        g_w1[o] = __float2half_rn(t[tx][ty + i]);
    }
}

// W2 [e][k=512][n=256] -> transposed fp16 [e][n][k]
__global__ void convert_w2_kernel(const float* __restrict__ W) {
    __shared__ float t[32][33];
    int e = blockIdx.z, k0 = blockIdx.x * 32, n0 = blockIdx.y * 32;
    int tx = threadIdx.x, ty = threadIdx.y;
    #pragma unroll
    for (int i = 0; i < 32; i += 8)
        t[ty + i][tx] = W[((size_t)e * DH + k0 + ty + i) * DOUT + n0 + tx];
    __syncthreads();
    #pragma unroll
    for (int i = 0; i < 32; i += 8) {
        size_t o = ((size_t)e * DOUT + n0 + ty + i) * DH + k0 + tx;
        g_w2[o] = __float2half_rn(t[tx][ty + i]);
    }
}

// ---------------- fused ffn: smem layout (dynamic, 230400 B) ----------------
#define SM_XA  0
#define SM_H   65536
#define SM_W   196608
#define SM_TOK 229376
#define SM_WT  229888
#define FSMEM  230400

__global__ __launch_bounds__(256, 1)
void ffn_fused_kernel(const float* __restrict__ b1, const float* __restrict__ b2,
                      float* __restrict__ out) {
    extern __shared__ __align__(16) char smem[];
    if ((int)blockIdx.x >= g_ntiles) return;
    int pk = g_tile[blockIdx.x];
    int e = pk >> 20, mbase = pk & 0xFFFFF;
    int cnt = g_cnt[e];

    int tid = threadIdx.x, lane = tid & 31, wid = tid >> 5;
    int* sTok = (int*)(smem + SM_TOK);
    float* sWt = (float*)(smem + SM_WT);
    if (tid < BM) {
        int li = min(mbase + tid, cnt - 1);
        sTok[tid] = g_tok[e * NB + li];
        sWt[tid] = g_wt[e * NB + li];
    }
    __syncthreads();

    uint32_t sxa = smem_to_u32(smem);
    uint32_t sH  = sxa + SM_H;
    uint32_t sW  = sxa + SM_W;

    const __half* w1p = g_w1 + (size_t)e * DH * DIN;
    const __half* w2p = g_w2 + (size_t)e * DOUT * DH;

    // preload full x tile + W1 chunk 0
    #pragma unroll
    for (int i = 0; i < 16; i++) {
        int idx = tid + i * 256;
        int row = idx >> 5, g = idx & 31;
        cp16(sxa + row * 512 + ((g ^ (row & 7)) << 4),
             g_x + (size_t)sTok[row] * DIN + g * 8);
    }
    #pragma unroll
    for (int i = 0; i < 4; i++) {
        int idx = tid + i * 256;
        int row = idx >> 3, g = idx & 7;
        cp16(sW + row * 128 + ((g ^ (row & 7)) << 4),
             w1p + (size_t)row * DIN + g * 8);
    }
    CP_COMMIT();

    int wm = (wid >> 1) * 32;
    int wn = (wid & 1) * 64;
    int t = lane >> 3;
    int bro  = ((t >> 1) << 3) + (lane & 7);
    int bco0 = (t & 1) * 16;
    float acc[2][8][4] = {};

    // ================= phase 1: H = relu(x @ W1T + b1) =================
    #pragma unroll
    for (int q = 0; q < 16; q++) {                         // nb = q>>2, c = q&3
        CP_WAIT0();
        __syncthreads();
        if (q < 15) {
            int nbN = (q + 1) >> 2, cN = (q + 1) & 3;
            uint32_t dst = sW + ((q + 1) & 1) * 16384;
            #pragma unroll
            for (int i = 0; i < 4; i++) {
                int idx = tid + i * 256;
                int row = idx >> 3, g = idx & 7;
                cp16(dst + row * 128 + ((g ^ (row & 7)) << 4),
                     w1p + (size_t)(nbN * 128 + row) * DIN + cN * 64 + g * 8);
            }
            CP_COMMIT();
        }
        uint32_t cB = sW + (q & 1) * 16384;
        #pragma unroll
        for (int kk = 0; kk < 4; kk++) {
            int colb = (q & 3) * 128 + kk * 32 + ((lane >> 4) << 4);
            int bcolb = kk * 32 + bco0;
            uint32_t ah[2][4], bh[4][4];
            #pragma unroll
            for (int f = 0; f < 2; f++) {
                int ar = wm + 16 * f + (lane & 15);
                ldmat4(ah[f], sxa + ar * 512 + (((colb >> 4) ^ (ar & 7)) << 4));
            }
            #pragma unroll
            for (int nf = 0; nf < 4; nf++) {
                int br = wn + 16 * nf + bro;
                ldmat4(bh[nf], cB + br * 128 + (((bcolb >> 4) ^ (br & 7)) << 4));
            }
            #pragma unroll
            for (int f = 0; f < 2; f++)
                #pragma unroll
                for (int nf = 0; nf < 4; nf++) {
                    mma16816(acc[f][nf * 2 + 0], ah[f], bh[nf] + 0);
                    mma16816(acc[f][nf * 2 + 1], ah[f], bh[nf] + 2);
                }
        }
        if ((q & 3) == 3) {                                // epilogue for nb
            int nb = q >> 2;
            #pragma unroll
            for (int f = 0; f < 2; f++) {
                #pragma unroll
                for (int hh = 0; hh < 2; hh++) {
                    int mrow = wm + f * 16 + (lane >> 2) + hh * 8;
                    #pragma unroll
                    for (int jn = 0; jn < 8; jn++) {
                        int cn = jn * 8 + (lane & 3) * 2;
                        int colf = nb * 128 + wn + cn;
                        float v0 = acc[f][jn][hh * 2 + 0] + b1[e * DH + colf];
                        float v1 = acc[f][jn][hh * 2 + 1] + b1[e * DH + colf + 1];
                        v0 = fmaxf(v0, 0.f); v1 = fmaxf(v1, 0.f);
                        int byte = colf * 2;
                        uint32_t ad = sH + mrow * 1024 +
                                      (((byte >> 4) ^ (mrow & 7)) << 4) + (byte & 12);
                        asm volatile("st.shared.b32 [%0], %1;" :: "r"(ad),
                                     "r"(pack2h(__float2half_rn(v0), __float2half_rn(v1))) : "memory");
                        acc[f][jn][hh * 2 + 0] = 0.f;
                        acc[f][jn][hh * 2 + 1] = 0.f;
                    }
                }
            }
        }
    }
    __syncthreads();                                       // H complete

    // issue W2 chunk 0 into buffer 0
    #pragma unroll
    for (int i = 0; i < 4; i++) {
        int idx = tid + i * 256;
        int row = idx >> 3, g = idx & 7;
        cp16(sW + row * 128 + ((g ^ (row & 7)) << 4),
             w2p + (size_t)row * DH + g * 8);
    }
    CP_COMMIT();

    // ================= phase 2: out += w * (H @ W2T + b2) =================
    #pragma unroll
    for (int q = 0; q < 16; q++) {                         // nb = q>>3, c = q&7
        CP_WAIT0();
        __syncthreads();
        if (q < 15) {
            int nbN = (q + 1) >> 3, cN = (q + 1) & 7;
            uint32_t dst = sW + ((q + 1) & 1) * 16384;
            #pragma unroll
            for (int i = 0; i < 4; i++) {
                int idx = tid + i * 256;
                int row = idx >> 3, g = idx & 7;
                cp16(dst + row * 128 + ((g ^ (row & 7)) << 4),
                     w2p + (size_t)(nbN * 128 + row) * DH + cN * 64 + g * 8);
            }
            CP_COMMIT();
        }
        uint32_t cB = sW + (q & 1) * 16384;
        #pragma unroll
        for (int kk = 0; kk < 4; kk++) {
            int colb = (q & 7) * 128 + kk * 32 + ((lane >> 4) << 4);
            int bcolb = kk * 32 + bco0;
            uint32_t ah[2][4], bh[4][4];
            #pragma unroll
            for (int f = 0; f < 2; f++) {
                int ar = wm + 16 * f + (lane & 15);
                ldmat4(ah[f], sH + ar * 1024 + (((colb >> 4) ^ (ar & 7)) << 4));
            }
            #pragma unroll
            for (int nf = 0; nf < 4; nf++) {
                int br = wn + 16 * nf + bro;
                ldmat4(bh[nf], cB + br * 128 + (((bcolb >> 4) ^ (br & 7)) << 4));
            }
            #pragma unroll
            for (int f = 0; f < 2; f++)
                #pragma unroll
                for (int nf = 0; nf < 4; nf++) {
                    mma16816(acc[f][nf * 2 + 0], ah[f], bh[nf] + 0);
                    mma16816(acc[f][nf * 2 + 1], ah[f], bh[nf] + 2);
                }
        }
        if ((q & 7) == 7) {                                // epilogue for nb
            int nb = q >> 3;
            #pragma unroll
            for (int f = 0; f < 2; f++) {
                #pragma unroll
                for (int hh = 0; hh < 2; hh++) {
                    int mloc = wm + f * 16 + (lane >> 2) + hh * 8;
                    if (mbase + mloc < cnt) {
                        int tok = sTok[mloc];
                        float w = sWt[mloc];
                        float* orow = out + (size_t)tok * DOUT + nb * 128 + wn;
                        #pragma unroll
                        for (int jn = 0; jn < 8; jn++) {
                            int cn = jn * 8 + (lane & 3) * 2;
                            float v0 = w * (acc[f][jn][hh * 2 + 0] + b2[e * DOUT + nb * 128 + wn + cn]);
                            float v1 = w * (acc[f][jn][hh * 2 + 1] + b2[e * DOUT + nb * 128 + wn + cn + 1]);
                            atomicAdd(orow + cn,     v0);
                            atomicAdd(orow + cn + 1, v1);
                        }
                    }
                    #pragma unroll
                    for (int jn = 0; jn < 8; jn++) {
                        acc[f][jn][hh * 2 + 0] = 0.f;
                        acc[f][jn][hh * 2 + 1] = 0.f;
                    }
                }
            }
        }
    }
}

// ---------------------------------------------------------------------------
extern "C" void kernel_launch(void* const* d_in, const int* in_sizes, int n_in,
                              void* d_out, int out_size) {
    (void)in_sizes; (void)n_in; (void)out_size;
    const float* x  = (const float*)d_in[0];
    const float* Wg = (const float*)d_in[1];
    const float* bg = (const float*)d_in[2];
    const float* W1 = (const float*)d_in[3];
    const float* b1 = (const float*)d_in[4];
    const float* W2 = (const float*)d_in[5];
    const float* b2 = (const float*)d_in[6];
    float* out = (float*)d_out;

    static cudaStream_t s2 = nullptr;
    static cudaEvent_t evA = nullptr, evB = nullptr;
    if (!s2) {
        cudaStreamCreateWithFlags(&s2, cudaStreamNonBlocking);
        cudaEventCreateWithFlags(&evA, cudaEventDisableTiming);
        cudaEventCreateWithFlags(&evB, cudaEventDisableTiming);
        cudaFuncSetAttribute(ffn_fused_kernel, cudaFuncAttributeMaxDynamicSharedMemorySize, FSMEM);
    }

    // fork: weight conversion + out-zeroing on s2, gating chain on capture stream
    cudaEventRecord(evA, 0);
    cudaStreamWaitEvent(s2, evA, 0);
    convert_w1_kernel<<<dim3(DIN / 32, DH / 32, NE), dim3(32, 8), 0, s2>>>(W1);
    convert_w2_kernel<<<dim3(DH / 32, DOUT / 32, NE), dim3(32, 8), 0, s2>>>(W2);
    cudaMemsetAsync(out, 0, (size_t)NB * DOUT * sizeof(float), s2);

    zero_cnt_kernel<<<1, 32>>>();
    gating_kernel<<<NB / 8, 256>>>(x, Wg, bg);
    build_tiles_kernel<<<1, 1>>>();

    // join
    cudaEventRecord(evB, s2);
    cudaStreamWaitEvent(0, evB, 0);

    ffn_fused_kernel<<<MAXT, 256, FSMEM>>>(b1, b2, out);
}

// round 13
// speedup vs baseline: 1.2186x; 1.2186x over previous
#include <cuda_runtime.h>
#include <cuda_fp16.h>
#include <cstdint>
#include <math.h>

#define NE    16
#define DIN   256
#define DH    512
#define DOUT  256
#define NB    32768
#define BM    128
#define MAXT  544

// ---------------- persistent device scratch ----------------
__device__ int   g_cnt[NE];
__device__ int   g_tok[NE * NB];
__device__ float g_wt [NE * NB];
__device__ int   g_ntiles;
__device__ int   g_tile[MAXT];                 // (e<<20) | mbase
__device__ __align__(16) __half g_x [NB * DIN];
__device__ __align__(16) __half g_w1[NE * DH * DIN];   // [e][n][k]
__device__ __align__(16) __half g_w2[NE * DOUT * DH];  // [e][n][k]

// ---------------- helpers ----------------
__device__ __forceinline__ uint32_t smem_to_u32(const void* p) {
    uint32_t a;
    asm("{ .reg .u64 t; cvta.to.shared.u64 t, %1; cvt.u32.u64 %0, t; }" : "=r"(a) : "l"(p));
    return a;
}
__device__ __forceinline__ void ldmat4(uint32_t* r, uint32_t addr) {
    asm volatile("ldmatrix.sync.aligned.m8n8.x4.shared.b16 {%0,%1,%2,%3}, [%4];"
        : "=r"(r[0]), "=r"(r[1]), "=r"(r[2]), "=r"(r[3]) : "r"(addr));
}
__device__ __forceinline__ void mma16816(float* c, const uint32_t* a, const uint32_t* b) {
    asm volatile("mma.sync.aligned.m16n8k16.row.col.f32.f16.f16.f32 "
        "{%0,%1,%2,%3},{%4,%5,%6,%7},{%8,%9},{%0,%1,%2,%3};"
        : "+f"(c[0]), "+f"(c[1]), "+f"(c[2]), "+f"(c[3])
        : "r"(a[0]), "r"(a[1]), "r"(a[2]), "r"(a[3]), "r"(b[0]), "r"(b[1]));
}
__device__ __forceinline__ uint32_t pack2h(__half a, __half b) {
    return (uint32_t)__half_as_ushort(a) | ((uint32_t)__half_as_ushort(b) << 16);
}
__device__ __forceinline__ void cp16(uint32_t s, const void* g) {
    asm volatile("cp.async.cg.shared.global [%0], [%1], 16;" :: "r"(s), "l"(g));
}
#define CP_COMMIT() asm volatile("cp.async.commit_group;" ::: "memory")
#define CP_WAIT0()  asm volatile("cp.async.wait_group 0;" ::: "memory")

// ---------------- small kernels ----------------
__global__ void zero_cnt_kernel() { if (threadIdx.x < NE) g_cnt[threadIdx.x] = 0; }

__global__ void build_tiles_kernel() {
    int nt = 0;
    for (int e = 0; e < NE; e++) {
        int c = g_cnt[e];
        for (int mb = 0; mb < c; mb += BM) g_tile[nt++] = (e << 20) | mb;
    }
    g_ntiles = nt;
}

// ---------------- gating: fp32 SIMT, thread-per-token, fused x->fp16 ----------
// Exact fp32 logits (top-k selection must not flip; fp16 logits proved fatal).
__global__ __launch_bounds__(128, 2)
void gating_kernel(const float* __restrict__ x,
                   const float* __restrict__ Wg,
                   const float* __restrict__ bg) {
    __shared__ float  sX[128][65];          // pad-65: bank = (t+k)&31, conflict-free
    __shared__ float4 sWg[64][4];           // [k][e4] chunk of Wg
    int tid = threadIdx.x;
    int tok0 = blockIdx.x * 128;

    float acc[NE] = {};
    for (int kc = 0; kc < DIN; kc += 64) {
        #pragma unroll
        for (int i = 0; i < 2; i++) {       // Wg chunk: 256 float4
            int idx = tid + i * 128;
            int k = idx >> 2, e4 = idx & 3;
            sWg[k][e4] = *(const float4*)(Wg + (size_t)(kc + k) * NE + e4 * 4);
        }
        #pragma unroll
        for (int i = 0; i < 16; i++) {      // X chunk: 2048 float4 + fp16 conversion
            int idx = tid + i * 128;
            int row = idx >> 4, c4 = idx & 15;
            float4 v = *(const float4*)(x + (size_t)(tok0 + row) * DIN + kc + c4 * 4);
            sX[row][c4 * 4 + 0] = v.x;
            sX[row][c4 * 4 + 1] = v.y;
            sX[row][c4 * 4 + 2] = v.z;
            sX[row][c4 * 4 + 3] = v.w;
            uint2 p;
            p.x = pack2h(__float2half_rn(v.x), __float2half_rn(v.y));
            p.y = pack2h(__float2half_rn(v.z), __float2half_rn(v.w));
            *(uint2*)(g_x + (size_t)(tok0 + row) * DIN + kc + c4 * 4) = p;
        }
        __syncthreads();
        #pragma unroll 8
        for (int k = 0; k < 64; k++) {
            float xv = sX[tid][k];
            float4 w0 = sWg[k][0], w1 = sWg[k][1], w2 = sWg[k][2], w3 = sWg[k][3];
            acc[0]  += xv * w0.x;  acc[1]  += xv * w0.y;
            acc[2]  += xv * w0.z;  acc[3]  += xv * w0.w;
            acc[4]  += xv * w1.x;  acc[5]  += xv * w1.y;
            acc[6]  += xv * w1.z;  acc[7]  += xv * w1.w;
            acc[8]  += xv * w2.x;  acc[9]  += xv * w2.y;
            acc[10] += xv * w2.z;  acc[11] += xv * w2.w;
            acc[12] += xv * w3.x;  acc[13] += xv * w3.y;
            acc[14] += xv * w3.z;  acc[15] += xv * w3.w;
        }
        __syncthreads();
    }

    // top-2 (first-index tie-break, matching jax.lax.top_k), sigmoid weights
    int token = tok0 + tid;
    float m1 = -1e30f, m2 = -1e30f; int i1 = 0, i2 = 0;
    #pragma unroll
    for (int e = 0; e < NE; e++) {
        float v = acc[e] + __ldg(bg + e);
        if (v > m1)      { m2 = m1; i2 = i1; m1 = v; i1 = e; }
        else if (v > m2) { m2 = v;  i2 = e; }
    }
    float r  = expf(m2 - m1);
    float w0 = 1.f / (1.f + r);
    float w1 = 1.f - w0;
    int p  = atomicAdd(&g_cnt[i1], 1);
    g_tok[i1 * NB + p] = token;  g_wt[i1 * NB + p] = w0;
    int p2 = atomicAdd(&g_cnt[i2], 1);
    g_tok[i2 * NB + p2] = token; g_wt[i2 * NB + p2] = w1;
}

// W1 [e][k=256][n=512] -> transposed fp16 [e][n][k]
__global__ void convert_w1_kernel(const float* __restrict__ W) {
    __shared__ float t[32][33];
    int e = blockIdx.z, k0 = blockIdx.x * 32, n0 = blockIdx.y * 32;
    int tx = threadIdx.x, ty = threadIdx.y;
    #pragma unroll
    for (int i = 0; i < 32; i += 8)
        t[ty + i][tx] = W[((size_t)e * DIN + k0 + ty + i) * DH + n0 + tx];
    __syncthreads();
    #pragma unroll
    for (int i = 0; i < 32; i += 8) {
        size_t o = ((size_t)e * DH + n0 + ty + i) * DIN + k0 + tx;
        g_w1[o] = __float2half_rn(t[tx][ty + i]);
    }
}

// W2 [e][k=512][n=256] -> transposed fp16 [e][n][k]
__global__ void convert_w2_kernel(const float* __restrict__ W) {
    __shared__ float t[32][33];
    int e = blockIdx.z, k0 = blockIdx.x * 32, n0 = blockIdx.y * 32;
    int tx = threadIdx.x, ty = threadIdx.y;
    #pragma unroll
    for (int i = 0; i < 32; i += 8)
        t[ty + i][tx] = W[((size_t)e * DH + k0 + ty + i) * DOUT + n0 + tx];
    __syncthreads();
    #pragma unroll
    for (int i = 0; i < 32; i += 8) {
        size_t o = ((size_t)e * DOUT + n0 + ty + i) * DH + k0 + tx;
        g_w2[o] = __float2half_rn(t[tx][ty + i]);
    }
}

// ---------------- fused ffn: smem layout (dynamic, 230400 B) ----------------
#define SM_XA  0
#define SM_H   65536
#define SM_W   196608
#define SM_TOK 229376
#define SM_WT  229888
#define FSMEM  230400

__global__ __launch_bounds__(256, 1)
void ffn_fused_kernel(const float* __restrict__ b1, const float* __restrict__ b2,
                      float* __restrict__ out) {
    extern __shared__ __align__(16) char smem[];
    if ((int)blockIdx.x >= g_ntiles) return;
    int pk = g_tile[blockIdx.x];
    int e = pk >> 20, mbase = pk & 0xFFFFF;
    int cnt = g_cnt[e];

    int tid = threadIdx.x, lane = tid & 31, wid = tid >> 5;
    int* sTok = (int*)(smem + SM_TOK);
    float* sWt = (float*)(smem + SM_WT);
    if (tid < BM) {
        int li = min(mbase + tid, cnt - 1);
        sTok[tid] = g_tok[e * NB + li];
        sWt[tid] = g_wt[e * NB + li];
    }
    __syncthreads();

    uint32_t sxa = smem_to_u32(smem);
    uint32_t sH  = sxa + SM_H;
    uint32_t sW  = sxa + SM_W;

    const __half* w1p = g_w1 + (size_t)e * DH * DIN;
    const __half* w2p = g_w2 + (size_t)e * DOUT * DH;

    #pragma unroll
    for (int i = 0; i < 16; i++) {
        int idx = tid + i * 256;
        int row = idx >> 5, g = idx & 31;
        cp16(sxa + row * 512 + ((g ^ (row & 7)) << 4),
             g_x + (size_t)sTok[row] * DIN + g * 8);
    }
    #pragma unroll
    for (int i = 0; i < 4; i++) {
        int idx = tid + i * 256;
        int row = idx >> 3, g = idx & 7;
        cp16(sW + row * 128 + ((g ^ (row & 7)) << 4),
             w1p + (size_t)row * DIN + g * 8);
    }
    CP_COMMIT();

    int wm = (wid >> 1) * 32;
    int wn = (wid & 1) * 64;
    int t = lane >> 3;
    int bro  = ((t >> 1) << 3) + (lane & 7);
    int bco0 = (t & 1) * 16;
    float acc[2][8][4] = {};

    // ================= phase 1: H = relu(x @ W1T + b1) =================
    #pragma unroll
    for (int q = 0; q < 16; q++) {                         // nb = q>>2, c = q&3
        CP_WAIT0();
        __syncthreads();
        if (q < 15) {
            int nbN = (q + 1) >> 2, cN = (q + 1) & 3;
            uint32_t dst = sW + ((q + 1) & 1) * 16384;
            #pragma unroll
            for (int i = 0; i < 4; i++) {
                int idx = tid + i * 256;
                int row = idx >> 3, g = idx & 7;
                cp16(dst + row * 128 + ((g ^ (row & 7)) << 4),
                     w1p + (size_t)(nbN * 128 + row) * DIN + cN * 64 + g * 8);
            }
            CP_COMMIT();
        }
        uint32_t cB = sW + (q & 1) * 16384;
        #pragma unroll
        for (int kk = 0; kk < 4; kk++) {
            int colb = (q & 3) * 128 + kk * 32 + ((lane >> 4) << 4);
            int bcolb = kk * 32 + bco0;
            uint32_t ah[2][4], bh[4][4];
            #pragma unroll
            for (int f = 0; f < 2; f++) {
                int ar = wm + 16 * f + (lane & 15);
                ldmat4(ah[f], sxa + ar * 512 + (((colb >> 4) ^ (ar & 7)) << 4));
            }
            #pragma unroll
            for (int nf = 0; nf < 4; nf++) {
                int br = wn + 16 * nf + bro;
                ldmat4(bh[nf], cB + br * 128 + (((bcolb >> 4) ^ (br & 7)) << 4));
            }
            #pragma unroll
            for (int f = 0; f < 2; f++)
                #pragma unroll
                for (int nf = 0; nf < 4; nf++) {
                    mma16816(acc[f][nf * 2 + 0], ah[f], bh[nf] + 0);
                    mma16816(acc[f][nf * 2 + 1], ah[f], bh[nf] + 2);
                }
        }
        if ((q & 3) == 3) {
            int nb = q >> 2;
            #pragma unroll
            for (int f = 0; f < 2; f++) {
                #pragma unroll
                for (int hh = 0; hh < 2; hh++) {
                    int mrow = wm + f * 16 + (lane >> 2) + hh * 8;
                    #pragma unroll
                    for (int jn = 0; jn < 8; jn++) {
                        int cn = jn * 8 + (lane & 3) * 2;
                        int colf = nb * 128 + wn + cn;
                        float v0 = acc[f][jn][hh * 2 + 0] + b1[e * DH + colf];
                        float v1 = acc[f][jn][hh * 2 + 1] + b1[e * DH + colf + 1];
                        v0 = fmaxf(v0, 0.f); v1 = fmaxf(v1, 0.f);
                        int byte = colf * 2;
                        uint32_t ad = sH + mrow * 1024 +
                                      (((byte >> 4) ^ (mrow & 7)) << 4) + (byte & 12);
                        asm volatile("st.shared.b32 [%0], %1;" :: "r"(ad),
                                     "r"(pack2h(__float2half_rn(v0), __float2half_rn(v1))) : "memory");
                        acc[f][jn][hh * 2 + 0] = 0.f;
                        acc[f][jn][hh * 2 + 1] = 0.f;
                    }
                }
            }
        }
    }
    __syncthreads();

    #pragma unroll
    for (int i = 0; i < 4; i++) {
        int idx = tid + i * 256;
        int row = idx >> 3, g = idx & 7;
        cp16(sW + row * 128 + ((g ^ (row & 7)) << 4),
             w2p + (size_t)row * DH + g * 8);
    }
    CP_COMMIT();

    // ================= phase 2: out += w * (H @ W2T + b2) =================
    #pragma unroll
    for (int q = 0; q < 16; q++) {                         // nb = q>>3, c = q&7
        CP_WAIT0();
        __syncthreads();
        if (q < 15) {
            int nbN = (q + 1) >> 3, cN = (q + 1) & 7;
            uint32_t dst = sW + ((q + 1) & 1) * 16384;
            #pragma unroll
            for (int i = 0; i < 4; i++) {
                int idx = tid + i * 256;
                int row = idx >> 3, g = idx & 7;
                cp16(dst + row * 128 + ((g ^ (row & 7)) << 4),
                     w2p + (size_t)(nbN * 128 + row) * DH + cN * 64 + g * 8);
            }
            CP_COMMIT();
        }
        uint32_t cB = sW + (q & 1) * 16384;
        #pragma unroll
        for (int kk = 0; kk < 4; kk++) {
            int colb = (q & 7) * 128 + kk * 32 + ((lane >> 4) << 4);
            int bcolb = kk * 32 + bco0;
            uint32_t ah[2][4], bh[4][4];
            #pragma unroll
            for (int f = 0; f < 2; f++) {
                int ar = wm + 16 * f + (lane & 15);
                ldmat4(ah[f], sH + ar * 1024 + (((colb >> 4) ^ (ar & 7)) << 4));
            }
            #pragma unroll
            for (int nf = 0; nf < 4; nf++) {
                int br = wn + 16 * nf + bro;
                ldmat4(bh[nf], cB + br * 128 + (((bcolb >> 4) ^ (br & 7)) << 4));
            }
            #pragma unroll
            for (int f = 0; f < 2; f++)
                #pragma unroll
                for (int nf = 0; nf < 4; nf++) {
                    mma16816(acc[f][nf * 2 + 0], ah[f], bh[nf] + 0);
                    mma16816(acc[f][nf * 2 + 1], ah[f], bh[nf] + 2);
                }
        }
        if ((q & 7) == 7) {
            int nb = q >> 3;
            #pragma unroll
            for (int f = 0; f < 2; f++) {
                #pragma unroll
                for (int hh = 0; hh < 2; hh++) {
                    int mloc = wm + f * 16 + (lane >> 2) + hh * 8;
                    if (mbase + mloc < cnt) {
                        int tok = sTok[mloc];
                        float w = sWt[mloc];
                        float* orow = out + (size_t)tok * DOUT + nb * 128 + wn;
                        #pragma unroll
                        for (int jn = 0; jn < 8; jn++) {
                            int cn = jn * 8 + (lane & 3) * 2;
                            float v0 = w * (acc[f][jn][hh * 2 + 0] + b2[e * DOUT + nb * 128 + wn + cn]);
                            float v1 = w * (acc[f][jn][hh * 2 + 1] + b2[e * DOUT + nb * 128 + wn + cn + 1]);
                            atomicAdd(orow + cn,     v0);
                            atomicAdd(orow + cn + 1, v1);
                        }
                    }
                    #pragma unroll
                    for (int jn = 0; jn < 8; jn++) {
                        acc[f][jn][hh * 2 + 0] = 0.f;
                        acc[f][jn][hh * 2 + 1] = 0.f;
                    }
                }
            }
        }
    }
}

// ---------------------------------------------------------------------------
extern "C" void kernel_launch(void* const* d_in, const int* in_sizes, int n_in,
                              void* d_out, int out_size) {
    (void)in_sizes; (void)n_in; (void)out_size;
    const float* x  = (const float*)d_in[0];
    const float* Wg = (const float*)d_in[1];
    const float* bg = (const float*)d_in[2];
    const float* W1 = (const float*)d_in[3];
    const float* b1 = (const float*)d_in[4];
    const float* W2 = (const float*)d_in[5];
    const float* b2 = (const float*)d_in[6];
    float* out = (float*)d_out;

    static cudaStream_t s2 = nullptr, s3 = nullptr;
    static cudaEvent_t evA = nullptr, evB = nullptr, evC = nullptr;
    if (!s2) {
        cudaStreamCreateWithFlags(&s2, cudaStreamNonBlocking);
        cudaStreamCreateWithFlags(&s3, cudaStreamNonBlocking);
        cudaEventCreateWithFlags(&evA, cudaEventDisableTiming);
        cudaEventCreateWithFlags(&evB, cudaEventDisableTiming);
        cudaEventCreateWithFlags(&evC, cudaEventDisableTiming);
        cudaFuncSetAttribute(ffn_fused_kernel, cudaFuncAttributeMaxDynamicSharedMemorySize, FSMEM);
    }

    // fork: weight conversion + out-zeroing on side streams
    cudaEventRecord(evA, 0);
    cudaStreamWaitEvent(s2, evA, 0);
    cudaStreamWaitEvent(s3, evA, 0);
    convert_w1_kernel<<<dim3(DIN / 32, DH / 32, NE), dim3(32, 8), 0, s2>>>(W1);
    cudaMemsetAsync(out, 0, (size_t)NB * DOUT * sizeof(float), s2);
    convert_w2_kernel<<<dim3(DH / 32, DOUT / 32, NE), dim3(32, 8), 0, s3>>>(W2);

    // main: gating (+x conversion, fp32-exact routing) and tile list
    zero_cnt_kernel<<<1, 32>>>();
    gating_kernel<<<NB / 128, 128>>>(x, Wg, bg);
    build_tiles_kernel<<<1, 1>>>();

    // join
    cudaEventRecord(evB, s2);
    cudaStreamWaitEvent(0, evB, 0);
    cudaEventRecord(evC, s3);
    cudaStreamWaitEvent(0, evC, 0);

    ffn_fused_kernel<<<MAXT, 256, FSMEM>>>(b1, b2, out);
}